// round 3
// baseline (speedup 1.0000x reference)
#include <cuda_runtime.h>
#include <math.h>

#define HEADS 8
#define DIM 64
#define DH 64
#define DK 24
#define DHK 3
#define B 4
#define H 128
#define W 128
#define NTOK (H*W)           // 16384

typedef unsigned long long ull;

// ---------------- scratch (static device allocations are allowed) ----------
__device__ float g_kinp[B * NTOK * DK];      // 6.29 MB
__device__ float g_SW[2 * B * 24 * 64];      // [0..6143]=S  [6144..12287]=W2

// ---------------- packed f32x2 helpers -------------------------------------
__device__ __forceinline__ ull pack2(float lo, float hi) {
    ull r; asm("mov.b64 %0, {%1,%2};" : "=l"(r) : "f"(lo), "f"(hi)); return r;
}
__device__ __forceinline__ void unpack2(ull v, float& lo, float& hi) {
    asm("mov.b64 {%0,%1}, %2;" : "=f"(lo), "=f"(hi) : "l"(v));
}
__device__ __forceinline__ void fma2(ull& d, ull a, ull b) {
    asm("fma.rn.f32x2 %0, %1, %2, %0;" : "+l"(d) : "l"(a), "l"(b));
}

__device__ __forceinline__ float gelu_exact(float x) {
    return 0.5f * x * (1.0f + erff(x * 0.70710678118654752f));
}

// ===========================================================================
// K1: k_inp = illu_map @ Wk  (written to g_kinp)  +  S[b] += k_inp^T @ x
// grid (128, 4)  block 256; each block handles 128 tokens of one batch.
// ===========================================================================
__global__ __launch_bounds__(256) void k1_kinp_S(
    const float* __restrict__ x, const float* __restrict__ im,
    const float* __restrict__ Wk)
{
    __shared__ __align__(16) float wk_s[576];
    __shared__ __align__(16) float k_s[128 * 24];
    __shared__ __align__(16) float x_s[128 * 64];

    const int tid = threadIdx.x;
    const int b = blockIdx.y;
    const int t0 = b * NTOK + blockIdx.x * 128;

    for (int i = tid; i < 576; i += 256) wk_s[i] = Wk[i];
    {
        const float* xg = x + (size_t)t0 * 64;
        #pragma unroll
        for (int i = tid; i < 8192; i += 256) x_s[i] = xg[i];
    }
    __syncthreads();

    // k_inp: 2 threads per token (each does 12 output channels)
    {
        const int tok = tid >> 1;
        const int j0 = (tid & 1) * 12;
        const float* img = im + (size_t)t0 * 24 + tok * 24;
        float acc[12];
        #pragma unroll
        for (int j = 0; j < 12; j++) acc[j] = 0.f;
        #pragma unroll 4
        for (int ci = 0; ci < 24; ci++) {
            float inv = img[ci];
            const float4* wp4 = (const float4*)&wk_s[ci * 24 + j0];
            float4 w0 = wp4[0], w1 = wp4[1], w2 = wp4[2];
            acc[0] += inv * w0.x; acc[1] += inv * w0.y; acc[2] += inv * w0.z; acc[3] += inv * w0.w;
            acc[4] += inv * w1.x; acc[5] += inv * w1.y; acc[6] += inv * w1.z; acc[7] += inv * w1.w;
            acc[8] += inv * w2.x; acc[9] += inv * w2.y; acc[10] += inv * w2.z; acc[11] += inv * w2.w;
        }
        #pragma unroll
        for (int j = 0; j < 12; j++) k_s[tok * 24 + j0 + j] = acc[j];
    }
    __syncthreads();

    // write k_inp coalesced
    {
        float* kg = g_kinp + (size_t)t0 * 24;
        #pragma unroll
        for (int i = tid; i < 3072; i += 256) kg[i] = k_s[i];
    }

    // S partial: thread owns j = jj*3+{0,1,2}, c = cc*2+{0,1}
    {
        const int jj = tid >> 5;        // warp id -> broadcast k loads
        const int cc = tid & 31;
        ull s0 = 0, s1 = 0, s2 = 0;
        const ull* xp = (const ull*)x_s;
        #pragma unroll 4
        for (int t = 0; t < 128; t++) {
            ull xv = xp[t * 32 + cc];
            float ka = k_s[t * 24 + jj * 3 + 0];
            float kb = k_s[t * 24 + jj * 3 + 1];
            float kc = k_s[t * 24 + jj * 3 + 2];
            fma2(s0, pack2(ka, ka), xv);
            fma2(s1, pack2(kb, kb), xv);
            fma2(s2, pack2(kc, kc), xv);
        }
        float lo, hi;
        float* Sg = g_SW + b * 1536;
        unpack2(s0, lo, hi);
        atomicAdd(&Sg[(jj * 3 + 0) * 64 + cc * 2], lo);
        atomicAdd(&Sg[(jj * 3 + 0) * 64 + cc * 2 + 1], hi);
        unpack2(s1, lo, hi);
        atomicAdd(&Sg[(jj * 3 + 1) * 64 + cc * 2], lo);
        atomicAdd(&Sg[(jj * 3 + 1) * 64 + cc * 2 + 1], hi);
        unpack2(s2, lo, hi);
        atomicAdd(&Sg[(jj * 3 + 2) * 64 + cc * 2], lo);
        atomicAdd(&Sg[(jj * 3 + 2) * 64 + cc * 2 + 1], hi);
    }
}

// ===========================================================================
// K2: logits -> softmax -> M -> W2 (atomicAdd).  grid (2,4) block 256.
// Block handles j-rows [half*12, half*12+12) i.e. heads [half*4, half*4+4).
// ===========================================================================
__global__ __launch_bounds__(256) void k2_attn_W2(
    const float* __restrict__ Wq, const float* __restrict__ Wv,
    const float* __restrict__ Wp, const float* __restrict__ rescale)
{
    __shared__ float s_S[12 * 64];
    __shared__ float s_A[12 * 64];
    __shared__ float s_M[64 * 12];

    const int half = blockIdx.x;
    const int b = blockIdx.y;
    const int tid = threadIdx.x;

    const float* Sg = g_SW + b * 1536 + half * 12 * 64;
    for (int i = tid; i < 768; i += 256) s_S[i] = Sg[i];
    __syncthreads();

    const int jj = tid >> 6;      // 0..3
    const int d = tid & 63;
    const int h = half * 4 + jj;

    // logits (3 rows share the same Wq column h*64+d)
    {
        float a0 = 0.f, a1 = 0.f, a2 = 0.f;
        const float* wqc = Wq + h * 64 + d;
        #pragma unroll 8
        for (int c = 0; c < 64; c++) {
            float wq = wqc[c * 512];
            a0 += s_S[(jj * 3 + 0) * 64 + c] * wq;
            a1 += s_S[(jj * 3 + 1) * 64 + c] * wq;
            a2 += s_S[(jj * 3 + 2) * 64 + c] * wq;
        }
        float sc = rescale[h] * 0.125f;
        s_A[(jj * 3 + 0) * 64 + d] = a0 * sc;
        s_A[(jj * 3 + 1) * 64 + d] = a1 * sc;
        s_A[(jj * 3 + 2) * 64 + d] = a2 * sc;
    }
    __syncthreads();

    // softmax over d for the 12 rows; one warp per row
    {
        const int wid = tid >> 5, lane = tid & 31;
        for (int row = wid; row < 12; row += 8) {
            float v0 = s_A[row * 64 + lane];
            float v1 = s_A[row * 64 + 32 + lane];
            float m = fmaxf(v0, v1);
            #pragma unroll
            for (int off = 16; off; off >>= 1) m = fmaxf(m, __shfl_xor_sync(~0u, m, off));
            float e0 = __expf(v0 - m), e1 = __expf(v1 - m);
            float s = e0 + e1;
            #pragma unroll
            for (int off = 16; off; off >>= 1) s += __shfl_xor_sync(~0u, s, off);
            float inv = 1.0f / s;
            s_A[row * 64 + lane] = e0 * inv;
            s_A[row * 64 + 32 + lane] = e1 * inv;
        }
    }
    __syncthreads();

    // M[c][jj*3+k] = sum_d Wv[c][h*64+d] * attn
    {
        const int c = tid & 63;
        float m0 = 0.f, m1 = 0.f, m2 = 0.f;
        const float* wvr = Wv + c * 512 + h * 64;
        #pragma unroll 8
        for (int dd = 0; dd < 64; dd++) {
            float wv = wvr[dd];
            m0 += wv * s_A[(jj * 3 + 0) * 64 + dd];
            m1 += wv * s_A[(jj * 3 + 1) * 64 + dd];
            m2 += wv * s_A[(jj * 3 + 2) * 64 + dd];
        }
        s_M[c * 12 + jj * 3 + 0] = m0;
        s_M[c * 12 + jj * 3 + 1] = m1;
        s_M[c * 12 + jj * 3 + 2] = m2;
    }
    __syncthreads();

    // W2[c][o] += sum over this block's 12 j2 of M[c][jl]*Wp[j2][o]
    {
        const int ce = tid >> 2;
        const int o0 = (tid & 3) * 6;
        float acc[6];
        #pragma unroll
        for (int u = 0; u < 6; u++) acc[u] = 0.f;
        #pragma unroll
        for (int jl = 0; jl < 12; jl++) {
            float m = s_M[ce * 12 + jl];
            int jjl = jl / 3, k = jl - jjl * 3;
            int j2 = k * 8 + half * 4 + jjl;
            const float* wp = Wp + j2 * 24 + o0;
            #pragma unroll
            for (int u = 0; u < 6; u++) acc[u] += m * wp[u];
        }
        float* W2g = g_SW + 6144 + b * 1536;
        #pragma unroll
        for (int u = 0; u < 6; u++) atomicAdd(&W2g[ce * 24 + o0 + u], acc[u]);
    }
}

// ===========================================================================
// K4: fused conv1 -> GELU -> conv2  +  projection fea@W2+bp, final write.
// grid (8,8,B) block 256, 16x16 pixel tile, dynamic smem.
// shared layout (floats): w1q[1728] w2q[1728] W2q[1536] kin[9600] t1[7776] bp[24]
// NOTE: gelu(conv1) is defined only on the image; conv2's SAME padding sees
// ZERO outside the image, so t1 entries with out-of-image coords are zeroed.
// ===========================================================================
#define S_W1 0
#define S_W2 1728
#define S_W2Q 3456
#define S_KIN 4992
#define S_T1 14592
#define S_BP 22368
#define K4_SMEM ((22368 + 32) * 4)

__global__ __launch_bounds__(256) void k4_conv_proj(
    const float* __restrict__ fea, const float* __restrict__ bp,
    const float* __restrict__ c1w, const float* __restrict__ c2w,
    float* __restrict__ out)
{
    extern __shared__ __align__(16) float smem[];
    float* w1q = smem + S_W1;
    float* w2q = smem + S_W2;
    float* W2q = smem + S_W2Q;
    float* kin = smem + S_KIN;
    float* t1 = smem + S_T1;
    float* bps = smem + S_BP;

    const int tid = threadIdx.x;
    const int b = blockIdx.z;
    const int gy0 = blockIdx.y * 16;
    const int gx0 = blockIdx.x * 16;

    // stage weights transposed: wq[(i*9+r)*24 + o] = w[o*72 + i*9 + r]
    for (int idx = tid; idx < 1728; idx += 256) {
        int o = idx % 24, r2 = idx / 24;
        w1q[r2 * 24 + o] = c1w[o * 72 + r2];
        w2q[r2 * 24 + o] = c2w[o * 72 + r2];
    }
    {
        const float* w2g = g_SW + 6144 + b * 1536;
        for (int idx = tid; idx < 1536; idx += 256) W2q[idx] = w2g[idx];
    }
    if (tid < 24) bps[tid] = bp[tid];

    // stage k_inp halo tile 20x20x24, zero-padded
    for (int idx = tid; idx < 9600; idx += 256) {
        int ch = idx % 24, rem = idx / 24;
        int xx = rem % 20, yy = rem / 20;
        int gy = gy0 - 2 + yy, gx = gx0 - 2 + xx;
        float v = 0.f;
        if (gy >= 0 && gy < H && gx >= 0 && gx < W)
            v = g_kinp[((size_t)b * NTOK + gy * W + gx) * 24 + ch];
        kin[(yy * 20 + xx) * 24 + ch] = v;
    }
    __syncthreads();

    // conv1 + GELU into t1 (18x18x24); zero outside the actual image
    for (int p = tid; p < 324; p += 256) {
        int yy = p / 18, xx = p - (p / 18) * 18;
        int gy = gy0 - 1 + yy, gx = gx0 - 1 + xx;
        bool inb = (gy >= 0 && gy < H && gx >= 0 && gx < W);
        ull acc[12];
        #pragma unroll
        for (int m = 0; m < 12; m++) acc[m] = 0ull;
        #pragma unroll
        for (int ky = 0; ky < 3; ky++) {
            #pragma unroll
            for (int kx = 0; kx < 3; kx++) {
                const float* inp = &kin[((yy + ky) * 20 + xx + kx) * 24];
                const int r = ky * 3 + kx;
                #pragma unroll
                for (int i = 0; i < 8; i++) {
                    float v0 = inp[i], v1 = inp[8 + i], v2 = inp[16 + i];
                    ull p0 = pack2(v0, v0), p1 = pack2(v1, v1), p2 = pack2(v2, v2);
                    const ulonglong2* wv = (const ulonglong2*)&w1q[(i * 9 + r) * 24];
                    #pragma unroll
                    for (int m = 0; m < 6; m++) {
                        ulonglong2 wp = wv[m];
                        ull pin = (m < 2) ? p0 : ((m < 4) ? p1 : p2);
                        fma2(acc[2 * m], wp.x, pin);
                        fma2(acc[2 * m + 1], wp.y, pin);
                    }
                }
            }
        }
        float* dst = &t1[(yy * 18 + xx) * 24];
        #pragma unroll
        for (int m = 0; m < 12; m++) {
            float lo, hi; unpack2(acc[m], lo, hi);
            dst[2 * m] = inb ? gelu_exact(lo) : 0.f;
            dst[2 * m + 1] = inb ? gelu_exact(hi) : 0.f;
        }
    }
    __syncthreads();

    // conv2 + projection; one pixel per thread
    {
        const int py = tid >> 4, px = tid & 15;
        ull acc[12];
        #pragma unroll
        for (int m = 0; m < 12; m++) acc[m] = 0ull;
        #pragma unroll
        for (int ky = 0; ky < 3; ky++) {
            #pragma unroll
            for (int kx = 0; kx < 3; kx++) {
                const float* inp = &t1[((py + ky) * 18 + px + kx) * 24];
                const int r = ky * 3 + kx;
                #pragma unroll
                for (int i = 0; i < 8; i++) {
                    float v0 = inp[i], v1 = inp[8 + i], v2 = inp[16 + i];
                    ull p0 = pack2(v0, v0), p1 = pack2(v1, v1), p2 = pack2(v2, v2);
                    const ulonglong2* wv = (const ulonglong2*)&w2q[(i * 9 + r) * 24];
                    #pragma unroll
                    for (int m = 0; m < 6; m++) {
                        ulonglong2 wp = wv[m];
                        ull pin = (m < 2) ? p0 : ((m < 4) ? p1 : p2);
                        fma2(acc[2 * m], wp.x, pin);
                        fma2(acc[2 * m + 1], wp.y, pin);
                    }
                }
            }
        }
        // projection: fea row (64 floats) @ W2[b]
        const float4* fea4 = (const float4*)(fea +
            ((size_t)b * NTOK + (size_t)(gy0 + py) * W + (gx0 + px)) * 64);
        #pragma unroll 4
        for (int c4 = 0; c4 < 16; c4++) {
            float4 f = fea4[c4];
            float fe[4] = {f.x, f.y, f.z, f.w};
            #pragma unroll
            for (int e = 0; e < 4; e++) {
                ull f2 = pack2(fe[e], fe[e]);
                const ulonglong2* wrow = (const ulonglong2*)&W2q[(c4 * 4 + e) * 24];
                #pragma unroll
                for (int m = 0; m < 6; m++) {
                    ulonglong2 wp = wrow[m];
                    fma2(acc[2 * m], wp.x, f2);
                    fma2(acc[2 * m + 1], wp.y, f2);
                }
            }
        }
        // stage result into kin (no longer read) for coalesced write
        float* stg = &kin[tid * 24];
        #pragma unroll
        for (int m = 0; m < 12; m++) {
            float lo, hi; unpack2(acc[m], lo, hi);
            stg[2 * m] = lo + bps[2 * m];
            stg[2 * m + 1] = hi + bps[2 * m + 1];
        }
    }
    __syncthreads();
    for (int idx = tid; idx < 6144; idx += 256) {
        int tt = idx / 24, ch = idx - (idx / 24) * 24;
        int py2 = tt >> 4, px2 = tt & 15;
        out[((size_t)b * NTOK + (size_t)(gy0 + py2) * W + (gx0 + px2)) * 24 + ch] =
            kin[tt * 24 + ch];
    }
}

// ===========================================================================
extern "C" void kernel_launch(void* const* d_in, const int* in_sizes, int n_in,
                              void* d_out, int out_size)
{
    const float* x = (const float*)d_in[0];
    const float* fea = (const float*)d_in[1];
    const float* im = (const float*)d_in[2];
    const float* Wq = (const float*)d_in[3];
    const float* Wk = (const float*)d_in[4];
    const float* Wv = (const float*)d_in[5];
    const float* rescale = (const float*)d_in[6];
    const float* Wp = (const float*)d_in[7];
    const float* bp = (const float*)d_in[8];
    const float* c1w = (const float*)d_in[9];
    const float* c2w = (const float*)d_in[10];
    float* out = (float*)d_out;

    void* swptr = nullptr;
    cudaGetSymbolAddress(&swptr, g_SW);
    cudaMemsetAsync(swptr, 0, sizeof(float) * 2 * B * 24 * 64, 0);

    cudaFuncSetAttribute(k4_conv_proj,
                         cudaFuncAttributeMaxDynamicSharedMemorySize, K4_SMEM);

    k1_kinp_S<<<dim3(128, B), 256>>>(x, im, Wk);
    k2_attn_W2<<<dim3(2, B), 256>>>(Wq, Wv, Wp, rescale);
    k4_conv_proj<<<dim3(8, 8, B), 256, K4_SMEM>>>(fea, bp, c1w, c2w, out);
}

// round 4
// speedup vs baseline: 3.2162x; 3.2162x over previous
#include <cuda_runtime.h>
#include <math.h>

#define HEADS 8
#define DIM 64
#define DH 64
#define DK 24
#define DHK 3
#define B 4
#define H 128
#define W 128
#define NTOK (H*W)           // 16384

typedef unsigned long long ull;

// ---------------- scratch ---------------------------------------------------
// g_kinp is PLANAR: [b][ch][y][x]
__device__ float g_kinp[B * DK * H * W];     // 6.29 MB
__device__ float g_SW[2 * B * 24 * 64];      // [0..6143]=S  [6144..12287]=W2

// ---------------- packed f32x2 helpers -------------------------------------
__device__ __forceinline__ ull pack2(float lo, float hi) {
    ull r; asm("mov.b64 %0, {%1,%2};" : "=l"(r) : "f"(lo), "f"(hi)); return r;
}
__device__ __forceinline__ void unpack2(ull v, float& lo, float& hi) {
    asm("mov.b64 {%0,%1}, %2;" : "=f"(lo), "=f"(hi) : "l"(v));
}
__device__ __forceinline__ void fma2(ull& d, ull a, ull b) {
    asm("fma.rn.f32x2 %0, %1, %2, %0;" : "+l"(d) : "l"(a), "l"(b));
}

__device__ __forceinline__ float gelu_exact(float x) {
    return 0.5f * x * (1.0f + erff(x * 0.70710678118654752f));
}

// ===========================================================================
// K1: k_inp = illu_map @ Wk (planar write) + S[b] += k_inp^T @ x
// grid (128 rows, B) block 256; one block = one image row (128 tokens).
// ===========================================================================
__global__ __launch_bounds__(256) void k1_kinp_S(
    const float* __restrict__ x, const float* __restrict__ im,
    const float* __restrict__ Wk)
{
    __shared__ __align__(16) float wk_s[576];
    __shared__ __align__(16) float im_s[128 * 25];
    __shared__ __align__(16) float k_s[128 * 25];
    __shared__ __align__(16) float x_s[128 * 64];

    const int tid = threadIdx.x;
    const int b = blockIdx.y;
    const int row = blockIdx.x;
    const int t0 = b * NTOK + row * 128;

    for (int i = tid; i < 576; i += 256) wk_s[i] = Wk[i];
    {
        const float4* xg = (const float4*)(x + (size_t)t0 * 64);
        float4* xs4 = (float4*)x_s;
        #pragma unroll
        for (int i = tid; i < 2048; i += 256) xs4[i] = xg[i];
    }
    {
        const float* img = im + (size_t)t0 * 24;
        #pragma unroll
        for (int i = tid; i < 3072; i += 256) {
            int tok = i / 24, ci = i - tok * 24;
            im_s[tok * 25 + ci] = img[i];
        }
    }
    __syncthreads();

    // k_inp: 2 threads per token (each does 12 output channels)
    {
        const int tok = tid >> 1;
        const int j0 = (tid & 1) * 12;
        float acc[12];
        #pragma unroll
        for (int j = 0; j < 12; j++) acc[j] = 0.f;
        #pragma unroll 4
        for (int ci = 0; ci < 24; ci++) {
            float inv = im_s[tok * 25 + ci];
            const float4* wp4 = (const float4*)&wk_s[ci * 24 + j0];
            float4 w0 = wp4[0], w1 = wp4[1], w2 = wp4[2];
            acc[0] += inv * w0.x; acc[1] += inv * w0.y; acc[2] += inv * w0.z; acc[3] += inv * w0.w;
            acc[4] += inv * w1.x; acc[5] += inv * w1.y; acc[6] += inv * w1.z; acc[7] += inv * w1.w;
            acc[8] += inv * w2.x; acc[9] += inv * w2.y; acc[10] += inv * w2.z; acc[11] += inv * w2.w;
        }
        #pragma unroll
        for (int j = 0; j < 12; j++) k_s[tok * 25 + j0 + j] = acc[j];
    }
    __syncthreads();

    // write k_inp PLANAR: per channel 128 contiguous floats (coalesced)
    {
        #pragma unroll
        for (int i = tid; i < 3072; i += 256) {
            int ch = i >> 7, xx = i & 127;
            g_kinp[(((size_t)b * 24 + ch) * H + row) * W + xx] = k_s[xx * 25 + ch];
        }
    }

    // S partial: warp jj owns j = jj*3+{0,1,2}; lane cc owns c = cc*2+{0,1}
    {
        const int jj = tid >> 5;
        const int cc = tid & 31;
        ull s0 = 0, s1 = 0, s2 = 0;
        const ull* xp = (const ull*)x_s;
        #pragma unroll 4
        for (int t = 0; t < 128; t++) {
            ull xv = xp[t * 32 + cc];
            float ka = k_s[t * 25 + jj * 3 + 0];
            float kb = k_s[t * 25 + jj * 3 + 1];
            float kc = k_s[t * 25 + jj * 3 + 2];
            fma2(s0, pack2(ka, ka), xv);
            fma2(s1, pack2(kb, kb), xv);
            fma2(s2, pack2(kc, kc), xv);
        }
        float lo, hi;
        float* Sg = g_SW + b * 1536;
        unpack2(s0, lo, hi);
        atomicAdd(&Sg[(jj * 3 + 0) * 64 + cc * 2], lo);
        atomicAdd(&Sg[(jj * 3 + 0) * 64 + cc * 2 + 1], hi);
        unpack2(s1, lo, hi);
        atomicAdd(&Sg[(jj * 3 + 1) * 64 + cc * 2], lo);
        atomicAdd(&Sg[(jj * 3 + 1) * 64 + cc * 2 + 1], hi);
        unpack2(s2, lo, hi);
        atomicAdd(&Sg[(jj * 3 + 2) * 64 + cc * 2], lo);
        atomicAdd(&Sg[(jj * 3 + 2) * 64 + cc * 2 + 1], hi);
    }
}

// ===========================================================================
// K2: logits -> softmax -> M -> W2 (atomicAdd).  grid (2,B) block 256.
// ===========================================================================
__global__ __launch_bounds__(256) void k2_attn_W2(
    const float* __restrict__ Wq, const float* __restrict__ Wv,
    const float* __restrict__ Wp, const float* __restrict__ rescale)
{
    __shared__ float s_S[12 * 64];
    __shared__ float s_A[12 * 64];
    __shared__ float s_M[64 * 12];

    const int half = blockIdx.x;
    const int b = blockIdx.y;
    const int tid = threadIdx.x;

    const float* Sg = g_SW + b * 1536 + half * 12 * 64;
    for (int i = tid; i < 768; i += 256) s_S[i] = Sg[i];
    __syncthreads();

    const int jj = tid >> 6;
    const int d = tid & 63;
    const int h = half * 4 + jj;

    {
        float a0 = 0.f, a1 = 0.f, a2 = 0.f;
        const float* wqc = Wq + h * 64 + d;
        #pragma unroll 8
        for (int c = 0; c < 64; c++) {
            float wq = wqc[c * 512];
            a0 += s_S[(jj * 3 + 0) * 64 + c] * wq;
            a1 += s_S[(jj * 3 + 1) * 64 + c] * wq;
            a2 += s_S[(jj * 3 + 2) * 64 + c] * wq;
        }
        float sc = rescale[h] * 0.125f;
        s_A[(jj * 3 + 0) * 64 + d] = a0 * sc;
        s_A[(jj * 3 + 1) * 64 + d] = a1 * sc;
        s_A[(jj * 3 + 2) * 64 + d] = a2 * sc;
    }
    __syncthreads();

    {
        const int wid = tid >> 5, lane = tid & 31;
        for (int rowi = wid; rowi < 12; rowi += 8) {
            float v0 = s_A[rowi * 64 + lane];
            float v1 = s_A[rowi * 64 + 32 + lane];
            float m = fmaxf(v0, v1);
            #pragma unroll
            for (int off = 16; off; off >>= 1) m = fmaxf(m, __shfl_xor_sync(~0u, m, off));
            float e0 = __expf(v0 - m), e1 = __expf(v1 - m);
            float s = e0 + e1;
            #pragma unroll
            for (int off = 16; off; off >>= 1) s += __shfl_xor_sync(~0u, s, off);
            float inv = 1.0f / s;
            s_A[rowi * 64 + lane] = e0 * inv;
            s_A[rowi * 64 + 32 + lane] = e1 * inv;
        }
    }
    __syncthreads();

    {
        const int c = tid & 63;
        float m0 = 0.f, m1 = 0.f, m2 = 0.f;
        const float* wvr = Wv + c * 512 + h * 64;
        #pragma unroll 8
        for (int dd = 0; dd < 64; dd++) {
            float wv = wvr[dd];
            m0 += wv * s_A[(jj * 3 + 0) * 64 + dd];
            m1 += wv * s_A[(jj * 3 + 1) * 64 + dd];
            m2 += wv * s_A[(jj * 3 + 2) * 64 + dd];
        }
        s_M[c * 12 + jj * 3 + 0] = m0;
        s_M[c * 12 + jj * 3 + 1] = m1;
        s_M[c * 12 + jj * 3 + 2] = m2;
    }
    __syncthreads();

    {
        const int ce = tid >> 2;
        const int o0 = (tid & 3) * 6;
        float acc[6];
        #pragma unroll
        for (int u = 0; u < 6; u++) acc[u] = 0.f;
        #pragma unroll
        for (int jl = 0; jl < 12; jl++) {
            float m = s_M[ce * 12 + jl];
            int jjl = jl / 3, k = jl - jjl * 3;
            int j2 = k * 8 + half * 4 + jjl;
            const float* wp = Wp + j2 * 24 + o0;
            #pragma unroll
            for (int u = 0; u < 6; u++) acc[u] += m * wp[u];
        }
        float* W2g = g_SW + 6144 + b * 1536;
        #pragma unroll
        for (int u = 0; u < 6; u++) atomicAdd(&W2g[ce * 24 + o0 + u], acc[u]);
    }
}

// ===========================================================================
// K4: planar conv1 -> GELU -> conv2  +  projection fea@W2+bp, final write.
// grid (8,8,B) block 256, 16x16 output tile.
// smem (floats): w1s[1728] w2s[1728] W2q[1536] bps[32] kin[24*400] t1[24*360]
// ===========================================================================
#define S4_W1 0
#define S4_W2 1728
#define S4_W2Q 3456
#define S4_BP 4992
#define S4_KIN 5024
#define S4_T1 14624
#define K4_FLOATS (14624 + 8640)
#define K4_SMEM (K4_FLOATS * 4)

__global__ __launch_bounds__(256) void k4_conv_proj(
    const float* __restrict__ fea, const float* __restrict__ bp,
    const float* __restrict__ c1w, const float* __restrict__ c2w,
    float* __restrict__ out)
{
    extern __shared__ __align__(16) float smem[];
    float* w1s = smem + S4_W1;
    float* w2s = smem + S4_W2;
    float* W2q = smem + S4_W2Q;
    float* bps = smem + S4_BP;
    float* kin = smem + S4_KIN;   // planar [24][20][20]
    float* t1 = smem + S4_T1;     // planar [24][18][20]

    const int tid = threadIdx.x;
    const int b = blockIdx.z;
    const int gy0 = blockIdx.y * 16;
    const int gx0 = blockIdx.x * 16;

    // weights are already [oc][i][3][3] = oc*72 + i*9 + r: copy raw
    for (int i = tid; i < 1728; i += 256) { w1s[i] = c1w[i]; w2s[i] = c2w[i]; }
    {
        const float* w2g = g_SW + 6144 + b * 1536;
        for (int i = tid; i < 1536; i += 256) W2q[i] = w2g[i];
    }
    if (tid < 24) bps[tid] = bp[tid];

    // stage kin planar, halo 20x20, zero-padded
    for (int idx = tid; idx < 9600; idx += 256) {
        int ch = idx / 400, rem = idx - ch * 400;
        int yy = rem / 20, xx = rem - yy * 20;
        int gy = gy0 - 2 + yy, gx = gx0 - 2 + xx;
        float v = 0.f;
        if ((unsigned)gy < (unsigned)H && (unsigned)gx < (unsigned)W)
            v = g_kinp[(((size_t)b * 24 + ch) * H + gy) * W + gx];
        kin[ch * 400 + yy * 20 + xx] = v;
    }
    __syncthreads();

    // conv1 + GELU -> t1 (zero outside image). unit = oc*18 + ry.
    for (int unit = tid; unit < 432; unit += 256) {
        int oc = unit / 18;
        int ry = unit - oc * 18;
        const float* kbase = kin + (oc >> 3) * (8 * 400);
        float a[18];
        #pragma unroll
        for (int q = 0; q < 18; q++) a[q] = 0.f;
        #pragma unroll
        for (int i = 0; i < 8; i++) {
            const float* wr = w1s + oc * 72 + i * 9;
            float wreg[9];
            #pragma unroll
            for (int q = 0; q < 9; q++) wreg[q] = wr[q];
            const float* r0 = kbase + i * 400 + ry * 20;
            #pragma unroll
            for (int ky = 0; ky < 3; ky++) {
                const float4* rp = (const float4*)(r0 + ky * 20);
                float rr[20];
                #pragma unroll
                for (int q = 0; q < 5; q++) {
                    float4 f = rp[q];
                    rr[q * 4] = f.x; rr[q * 4 + 1] = f.y;
                    rr[q * 4 + 2] = f.z; rr[q * 4 + 3] = f.w;
                }
                float wa = wreg[ky * 3], wb = wreg[ky * 3 + 1], wc = wreg[ky * 3 + 2];
                #pragma unroll
                for (int xq = 0; xq < 18; xq++)
                    a[xq] += wa * rr[xq] + wb * rr[xq + 1] + wc * rr[xq + 2];
            }
        }
        int gy = gy0 - 1 + ry;
        bool rowin = (unsigned)gy < (unsigned)H;
        float* dst = t1 + oc * 360 + ry * 20;
        #pragma unroll
        for (int xq = 0; xq < 18; xq++) {
            int gx = gx0 - 1 + xq;
            dst[xq] = (rowin && (unsigned)gx < (unsigned)W) ? gelu_exact(a[xq]) : 0.f;
        }
    }
    __syncthreads();

    // conv2 -> c2o (reuse kin region): [24][16][16]. unit = oc*16 + ry.
    float* c2o = kin;
    for (int unit = tid; unit < 384; unit += 256) {
        int oc = unit >> 4;
        int ry = unit & 15;
        const float* tbase = t1 + (oc >> 3) * (8 * 360);
        float a[16];
        #pragma unroll
        for (int q = 0; q < 16; q++) a[q] = 0.f;
        #pragma unroll
        for (int i = 0; i < 8; i++) {
            const float* wr = w2s + oc * 72 + i * 9;
            float wreg[9];
            #pragma unroll
            for (int q = 0; q < 9; q++) wreg[q] = wr[q];
            const float* r0 = tbase + i * 360 + ry * 20;
            #pragma unroll
            for (int ky = 0; ky < 3; ky++) {
                const float4* rp = (const float4*)(r0 + ky * 20);
                float rr[20];
                #pragma unroll
                for (int q = 0; q < 5; q++) {
                    float4 f = rp[q];
                    rr[q * 4] = f.x; rr[q * 4 + 1] = f.y;
                    rr[q * 4 + 2] = f.z; rr[q * 4 + 3] = f.w;
                }
                float wa = wreg[ky * 3], wb = wreg[ky * 3 + 1], wc = wreg[ky * 3 + 2];
                #pragma unroll
                for (int xq = 0; xq < 16; xq++)
                    a[xq] += wa * rr[xq] + wb * rr[xq + 1] + wc * rr[xq + 2];
            }
        }
        float* dst = c2o + oc * 256 + ry * 16;
        #pragma unroll
        for (int q = 0; q < 16; q++) dst[q] = a[q];
    }
    __syncthreads();

    // projection: out = fea @ W2[b] + bp + c2o ; one pixel per thread
    {
        const int py = tid >> 4, px = tid & 15;
        ull acc[12];
        #pragma unroll
        for (int m = 0; m < 12; m++) acc[m] = 0ull;
        const float4* fea4 = (const float4*)(fea +
            ((size_t)b * NTOK + (size_t)(gy0 + py) * W + (gx0 + px)) * 64);
        #pragma unroll 4
        for (int c4 = 0; c4 < 16; c4++) {
            float4 f = fea4[c4];
            float fe[4] = {f.x, f.y, f.z, f.w};
            #pragma unroll
            for (int e = 0; e < 4; e++) {
                ull f2 = pack2(fe[e], fe[e]);
                const ulonglong2* wrow = (const ulonglong2*)&W2q[(c4 * 4 + e) * 24];
                #pragma unroll
                for (int m = 0; m < 6; m++) {
                    ulonglong2 wp = wrow[m];
                    fma2(acc[2 * m], wp.x, f2);
                    fma2(acc[2 * m + 1], wp.y, f2);
                }
            }
        }
        float res[24];
        #pragma unroll
        for (int m = 0; m < 12; m++) {
            float lo, hi; unpack2(acc[m], lo, hi);
            res[2 * m] = lo + bps[2 * m];
            res[2 * m + 1] = hi + bps[2 * m + 1];
        }
        #pragma unroll
        for (int ch = 0; ch < 24; ch++)
            res[ch] += c2o[ch * 256 + py * 16 + px];
        float4* og = (float4*)(out +
            ((size_t)b * NTOK + (size_t)(gy0 + py) * W + (gx0 + px)) * 24);
        #pragma unroll
        for (int q = 0; q < 6; q++)
            og[q] = make_float4(res[q * 4], res[q * 4 + 1], res[q * 4 + 2], res[q * 4 + 3]);
    }
}

// ===========================================================================
extern "C" void kernel_launch(void* const* d_in, const int* in_sizes, int n_in,
                              void* d_out, int out_size)
{
    const float* x = (const float*)d_in[0];
    const float* fea = (const float*)d_in[1];
    const float* im = (const float*)d_in[2];
    const float* Wq = (const float*)d_in[3];
    const float* Wk = (const float*)d_in[4];
    const float* Wv = (const float*)d_in[5];
    const float* rescale = (const float*)d_in[6];
    const float* Wp = (const float*)d_in[7];
    const float* bp = (const float*)d_in[8];
    const float* c1w = (const float*)d_in[9];
    const float* c2w = (const float*)d_in[10];
    float* out = (float*)d_out;

    void* swptr = nullptr;
    cudaGetSymbolAddress(&swptr, g_SW);
    cudaMemsetAsync(swptr, 0, sizeof(float) * 2 * B * 24 * 64, 0);

    cudaFuncSetAttribute(k4_conv_proj,
                         cudaFuncAttributeMaxDynamicSharedMemorySize, K4_SMEM);

    k1_kinp_S<<<dim3(128, B), 256>>>(x, im, Wk);
    k2_attn_W2<<<dim3(2, B), 256>>>(Wq, Wv, Wp, rescale);
    k4_conv_proj<<<dim3(8, 8, B), 256, K4_SMEM>>>(fea, bp, c1w, c2w, out);
}